// round 11
// baseline (speedup 1.0000x reference)
#include <cuda_runtime.h>
#include <cuda_bf16.h>

// PCEN: out = (E / (eps + M)^alpha + delta)^r - delta^r
// with causal EMA M_t = (1-s) M_{t-1} + s E_t, per (B,C) row over T.
//
// R9 post-mortem: register-resident version hit 35.5us with L1 = 63.6% the
// top unit. Cause (quantified): 64B per-thread stride makes every LDG/STG.128
// touch 16 lines -> 4x wavefront inflation (~22us L1 busy, matches ncu).
// Fix: CHUNK 16->8 (32B/thread stride) halves the inflation (2 instr x 8
// lines vs 4 x 16) for both loads and stores. THREADS 256->512 keeps one
// block per row. Everything else from R9 kept: no data smem, param table
// via prep kernel, register scan, direct STG.
//
// Scan: thread-local (8) -> warp shuffle scan (ratio A=a^8) -> serial
// 16-warp carry (ratio A^32 = a^256) -> recompute with true incoming state.
//
// r == 0.5f exactly here (log_r = inv_sigmoid(0.5) = 0) -> u^r is one
// MUFU.SQRT (uniform runtime check; __powf fallback kept).

#define T_LEN   4000
#define THREADS 512
#define CHUNK   8
#define NCHUNK  (T_LEN / CHUNK)   // 500
#define NWARP   (THREADS / 32)    // 16
#define EPS     1e-6f
#define MAX_C   1024

// per-channel: {s, a, -alpha, delta, dr, r, pad, pad}
__device__ float g_param_tab[MAX_C * 8];

__device__ __forceinline__ float sqrt_approx(float x) {
    float y;
    asm("sqrt.approx.f32 %0, %1;" : "=f"(y) : "f"(x));
    return y;
}

__global__ void pcen_prep(const float* __restrict__ log_alpha,
                          const float* __restrict__ log_delta,
                          const float* __restrict__ log_r,
                          const float* __restrict__ log_s,
                          int C)
{
    int c = blockIdx.x * blockDim.x + threadIdx.x;
    if (c < C) {
        float s     = 1.0f / (1.0f + __expf(-log_s[c]));
        float alpha = 1.0f / (1.0f + __expf(-log_alpha[c]));
        float delta = __logf(1.0f + __expf(log_delta[c]));
        float r     = 1.0f / (1.0f + __expf(-log_r[c]));
        float dr    = __powf(delta, r);
        float* p = &g_param_tab[c * 8];
        p[0] = s;
        p[1] = 1.0f - s;
        p[2] = -alpha;
        p[3] = delta;
        p[4] = dr;
        p[5] = r;
    }
}

__global__ __launch_bounds__(THREADS)
void pcen_kernel(const float* __restrict__ E,
                 float* __restrict__ out,
                 int C)
{
    __shared__ float warp_sum[NWARP];
    __shared__ float warp_pref[NWARP];

    const int row = blockIdx.x;            // b*C + c
    const int c   = row % C;

    const int tid  = threadIdx.x;
    const int lane = tid & 31;
    const int wid  = tid >> 5;

    // --- per-channel params from table (cached, broadcast) ---
    const float4 P0 = *(const float4*)&g_param_tab[c * 8];
    const float2 P1 = *(const float2*)&g_param_tab[c * 8 + 4];
    const float s      = P0.x;
    const float a      = P0.y;
    const float nalpha = P0.z;   // -alpha
    const float delta  = P0.w;
    const float dr     = P1.x;
    const float r      = P1.y;

    // --- direct register load: thread t owns elements [t*8, t*8+8) ---
    float ev[CHUNK];
    float local = 0.0f;
    const bool active = (tid < NCHUNK);
    const float4* src = (const float4*)(E + (size_t)row * T_LEN) + tid * 2;
    if (active) {
        float4 v0 = __ldg(src + 0);
        float4 v1 = __ldg(src + 1);
        ev[0]=v0.x; ev[1]=v0.y; ev[2]=v0.z; ev[3]=v0.w;
        ev[4]=v1.x; ev[5]=v1.y; ev[6]=v1.z; ev[7]=v1.w;
        #pragma unroll
        for (int k = 0; k < CHUNK; k++) {
            local = __fmaf_rn(a, local, s * ev[k]);
        }
    }

    // A = a^8 (chunk ratio)
    float A = a * a;          // a^2
    A = A * A;                // a^4
    A = A * A;                // a^8

    // --- warp Hillis-Steele scan of p_i = A * p_{i-1} + local_i ---
    // Apow = A^lane built from the doubling w for free.
    float p = local;
    float w = A;              // A^(2^k)
    float Apow = 1.0f;        // A^lane
    #pragma unroll
    for (int d = 1; d < 32; d <<= 1) {
        float up = __shfl_up_sync(0xffffffffu, p, d);
        if (lane >= d) p += w * up;
        if (lane & d)  Apow *= w;
        w = w * w;
    }
    const float A32 = w;      // A^32 = a^256 (per-warp ratio)

    // exclusive prefix within warp
    float pe = __shfl_up_sync(0xffffffffu, p, 1);
    if (lane == 0) pe = 0.0f;

    if (lane == 31) warp_sum[wid] = p;
    __syncthreads();

    // serial carry across the 16 warps (ratio A32), exclusive
    if (tid == 0) {
        float acc = 0.0f;
        #pragma unroll
        for (int j = 0; j < NWARP; j++) {
            warp_pref[j] = acc;
            acc = __fmaf_rn(A32, acc, warp_sum[j]);
        }
    }
    __syncthreads();

    // --- pass 2: recompute with true incoming state, apply PCEN math,
    //     store straight from registers ---
    if (active) {
        float m = __fmaf_rn(Apow, warp_pref[wid], pe);  // M before this chunk
        if (r == 0.5f) {
            #pragma unroll
            for (int k = 0; k < CHUNK; k++) {
                m = __fmaf_rn(a, m, s * ev[k]);
                float x  = EPS + m;
                float pw = __expf(nalpha * __logf(x));  // x^{-alpha}
                float u  = __fmaf_rn(ev[k], pw, delta);
                ev[k]    = sqrt_approx(u) - dr;         // u^0.5
            }
        } else {
            #pragma unroll
            for (int k = 0; k < CHUNK; k++) {
                m = __fmaf_rn(a, m, s * ev[k]);
                float x  = EPS + m;
                float pw = __powf(x, nalpha);
                float u  = __fmaf_rn(ev[k], pw, delta);
                ev[k]    = __powf(u, r) - dr;
            }
        }
        float4* dst = (float4*)(out + (size_t)row * T_LEN) + tid * 2;
        float4 o0 = {ev[0], ev[1], ev[2], ev[3]};
        float4 o1 = {ev[4], ev[5], ev[6], ev[7]};
        dst[0] = o0;
        dst[1] = o1;
    }
}

extern "C" void kernel_launch(void* const* d_in, const int* in_sizes, int n_in,
                              void* d_out, int out_size)
{
    const float* E         = (const float*)d_in[0];
    const float* log_alpha = (const float*)d_in[1];
    const float* log_delta = (const float*)d_in[2];
    const float* log_r     = (const float*)d_in[3];
    const float* log_s     = (const float*)d_in[4];
    float*       out       = (float*)d_out;

    const int C    = in_sizes[1];
    const int rows = in_sizes[0] / T_LEN;   // B*C

    pcen_prep<<<(C + 63) / 64, 64>>>(log_alpha, log_delta, log_r, log_s, C);
    pcen_kernel<<<rows, THREADS>>>(E, out, C);
}